// round 7
// baseline (speedup 1.0000x reference)
#include <cuda_runtime.h>
#include <cuda_bf16.h>

#define NN 16384      // nodes/edges (and bond_n rows A = 16384)
#define DD 128        // emb dim
// Only layer i = 2 matters: the reference loop does not feed h back.

#define NBLK 296      // 2 blocks per SM on 148 SMs -> all co-resident

// Scratch (device globals — zero-initialized at module load)
__device__ float g_colw[NN];
__device__ float g_mpartT[DD][128];          // m partials, contiguous per d
__device__ unsigned g_zc;                    // zero-flag counter   (0 -> 64)
__device__ unsigned g_b1;                    // barrier 1 counter   (0 -> 296)
__device__ unsigned g_b2;                    // barrier 2 counter   (0 -> 128)
__device__ unsigned g_done;                  // exit counter; last resets all

// Poll with a VOLATILE LOAD (L2 load path, broadcastable) — never with an
// atomic: same-address atomic polling serializes at the LTS atomic ALU and
// stalls the arrivals themselves (the R5/R6 barrier pathology).
__device__ __forceinline__ void bar_arrive(unsigned* c) {
    __syncthreads();
    if (threadIdx.x == 0) { __threadfence(); atomicAdd(c, 1u); }
}
__device__ __forceinline__ void bar_wait(unsigned* c, unsigned target) {
    if (threadIdx.x == 0) {
        volatile unsigned* vc = c;
        while (*vc < target) __nanosleep(128);
        __threadfence();
    }
    __syncthreads();
}

// ---------------------------------------------------------------------------
// Single kernel, 296 blocks:
//  entry: blocks 0..63 zero g_colw (flag g_zc).
//  P1a:   blocks [0,128) GEMM h_n = relu(cat @ Wi_w[2].T + b) -> SMEM only.
//  P1b:   all blocks stream static bond_n row shares, column partials in regs,
//         then (after g_zc>=64, long since done) REDG-atomicAdd into g_colw.
//  B1(296): non-GEMM blocks arrive + exit; GEMM blocks wait (colw complete).
//  P3:    GEMM blocks: m partial from SMEM h_n -> g_mpartT.
//  B2(128): GEMM blocks only.
//  P4:    redundant L2-hot m reduce + mm GEMV; out = relu(h_n + mm) from SMEM.
// ---------------------------------------------------------------------------
__global__ void __launch_bounds__(256, 2) k_all(
    const float* __restrict__ bn,
    const int* __restrict__ x, const int* __restrict__ ea,
    const float* __restrict__ aemb, const float* __restrict__ bemb,
    const float* __restrict__ Wi_w2, const float* __restrict__ Wi_b2,
    const float* __restrict__ Wm_w2, const float* __restrict__ Wm_b2,
    float* __restrict__ out)
{
    extern __shared__ float sm[];               // 65,792 B dynamic
    __shared__ float bias_s[128];
    __shared__ float colw_s[128];
    __shared__ float red[256];
    __shared__ float mm_s[128];
    __shared__ int xi0[128], xi1[128], ei0[128], ei1[128];

    const int tid = threadIdx.x;
    const int bid = blockIdx.x;
    const bool isGemm = (bid < 128);

    // ---- zero g_colw (blocks 0..63, 256 floats each) ----
    if (bid < 64) {
        g_colw[bid * 256 + tid] = 0.f;
        __syncthreads();
        if (tid == 0) { __threadfence(); atomicAdd(&g_zc, 1u); }
    }

    // ---- static row shares for the bond_n stream (sum = 16384) ----
    int start, cnt;
    if (bid < 128)          { start = bid * 51;                 cnt = 51; }
    else if (bid < 240)     { start = 6528  + (bid - 128) * 59; cnt = 59; }
    else                    { start = 13136 + (bid - 240) * 58; cnt = 58; }

    // =============== P1a: GEMM -> h_n in SMEM ===============
    if (isGemm) {
        float* w_s   = sm;                 // [64][129] = 33,024 B (per-k chunk)
        float* cat_s = sm + 64 * 129;      // [128][64] = 32,768 B
        const int rowBase = bid * 128;

        if (tid < 128) {
            bias_s[tid] = Wi_b2[tid];
            int r = rowBase + tid;
            xi0[tid] = x[2 * r];  xi1[tid] = x[2 * r + 1];
            ei0[tid] = ea[2 * r]; ei1[tid] = ea[2 * r + 1];
        }
        __syncthreads();

        const int tx = tid & 15, ty = tid >> 4;
        float acc[8][8];
#pragma unroll
        for (int i = 0; i < 8; i++)
#pragma unroll
            for (int j = 0; j < 8; j++) acc[i][j] = 0.f;

        for (int kc = 0; kc < 256; kc += 64) {
            for (int idx = tid; idx < 8192; idx += 256) {
                int d = idx >> 6, kk = idx & 63;
                w_s[kk * 129 + d] = Wi_w2[d * 256 + kc + kk];
            }
            const bool atom = (kc < 128);
            const float* emb = atom ? aemb : bemb;
            for (int idx = tid; idx < 2048; idx += 256) {
                int row  = idx >> 4;
                int kloc = (idx & 15) * 4;
                int i0 = atom ? xi0[row] : ei0[row];
                int i1 = atom ? xi1[row] : ei1[row];
                int ko = atom ? (kc + kloc) : (kc - 128 + kloc);
                float4 v0 = *(const float4*)(emb + i0 * 128 + ko);
                float4 v1 = *(const float4*)(emb + i1 * 128 + ko);
                float4 s;
                s.x = v0.x + v1.x; s.y = v0.y + v1.y;
                s.z = v0.z + v1.z; s.w = v0.w + v1.w;
                *(float4*)(cat_s + row * 64 + kloc) = s;
            }
            __syncthreads();

#pragma unroll 8
            for (int kk = 0; kk < 64; kk++) {
                const float* wr = w_s + kk * 129;
                float b[8], a[8];
#pragma unroll
                for (int j = 0; j < 8; j++) b[j] = wr[tx + 16 * j];
#pragma unroll
                for (int i = 0; i < 8; i++) a[i] = cat_s[(ty + 16 * i) * 64 + kk];
#pragma unroll
                for (int i = 0; i < 8; i++)
#pragma unroll
                    for (int j = 0; j < 8; j++)
                        acc[i][j] = fmaf(a[i], b[j], acc[i][j]);
            }
            __syncthreads();
        }

        // bias + relu -> h_n parked in SMEM (reuses w_s/cat_s space)
        float* hn = sm;                    // [128][128] = 65,536 B
#pragma unroll
        for (int i = 0; i < 8; i++) {
            int r = ty + 16 * i;
#pragma unroll
            for (int j = 0; j < 8; j++) {
                int d = tx + 16 * j;
                float v = acc[i][j] + bias_s[d];
                hn[r * 128 + d] = v > 0.f ? v : 0.f;
            }
        }
        __syncthreads();
    }

    // =============== P1b: bond_n streaming (ALL blocks) ===============
    {
        float4 acc[16];
#pragma unroll
        for (int i = 0; i < 16; i++) acc[i] = make_float4(0.f, 0.f, 0.f, 0.f);

        for (int r = 0; r < cnt; r++) {
            const float4* rp = (const float4*)(bn + (size_t)(start + r) * NN) + tid;
#pragma unroll
            for (int i = 0; i < 16; i++) {
                float4 v = __ldcs(rp + i * 256);
                acc[i].x += v.x; acc[i].y += v.y; acc[i].z += v.z; acc[i].w += v.w;
            }
        }

        // zeroing finished ~150us ago; volatile poll is instant
        if (tid == 0) {
            volatile unsigned* vz = &g_zc;
            while (*vz < 64u) __nanosleep(64);
        }
        __syncthreads();
        __threadfence();

        // spread-address REDG adds: column base = (tid + i*256)*4
#pragma unroll
        for (int i = 0; i < 16; i++) {
            int c = (tid + i * 256) * 4;
            atomicAdd(&g_colw[c + 0], acc[i].x);
            atomicAdd(&g_colw[c + 1], acc[i].y);
            atomicAdd(&g_colw[c + 2], acc[i].z);
            atomicAdd(&g_colw[c + 3], acc[i].w);
        }
    }

    bar_arrive(&g_b1);

    if (!isGemm) {
        // done; last of 296 resets all counters for next graph replay
        if (tid == 0) {
            unsigned r = atomicAdd(&g_done, 1u);
            if (r == NBLK - 1u) {
                g_zc = 0u; g_b1 = 0u; g_b2 = 0u;
                __threadfence();
                g_done = 0u;
            }
        }
        return;
    }

    bar_wait(&g_b1, NBLK);    // colw complete

    // =============== P3: m partial from SMEM h_n ===============
    const float* hn = sm;
    const int rowBase = bid * 128;
    if (tid < 128) colw_s[tid] = g_colw[rowBase + tid];
    __syncthreads();
    {
        const int d = tid & 127, half = tid >> 7;
        float p = 0.f;
#pragma unroll 8
        for (int r = 0; r < 64; r++) {
            int row = half * 64 + r;
            p = fmaf(colw_s[row], hn[row * 128 + d], p);
        }
        red[tid] = p;
    }
    __syncthreads();
    if (tid < 128) g_mpartT[tid][bid] = red[tid] + red[tid + 128];

    bar_arrive(&g_b2);
    bar_wait(&g_b2, 128u);

    // =============== P4: m reduce + mm GEMV + out (from SMEM) ===============
    if (tid < 128) {
        const float4* mp = (const float4*)g_mpartT[tid];
        float s = 0.f;
#pragma unroll 32
        for (int w = 0; w < 32; w++) {
            float4 v = __ldcg(mp + w);
            s += v.x + v.y + v.z + v.w;
        }
        red[tid] = s;        // red = m
    }
    __syncthreads();
    if (tid < 128) {
        float s = Wm_b2[tid];
        const float* row = Wm_w2 + tid * 128;
#pragma unroll 8
        for (int k = 0; k < 128; k++) s = fmaf(red[k], __ldg(row + k), s);
        mm_s[tid] = s;
    }
    __syncthreads();

    {
        float4* ob = (float4*)(out + (size_t)rowBase * 128);
#pragma unroll 4
        for (int i = tid; i < 4096; i += 256) {
            int row = i >> 5, dg = (i & 31) * 4;
            float4 v = *(const float4*)(hn + row * 128 + dg);
            v.x = fmaxf(v.x + mm_s[dg + 0], 0.f);
            v.y = fmaxf(v.y + mm_s[dg + 1], 0.f);
            v.z = fmaxf(v.z + mm_s[dg + 2], 0.f);
            v.w = fmaxf(v.w + mm_s[dg + 3], 0.f);
            ob[i] = v;
        }
    }

    __syncthreads();
    if (tid == 0) {
        unsigned r = atomicAdd(&g_done, 1u);
        if (r == NBLK - 1u) {
            g_zc = 0u; g_b1 = 0u; g_b2 = 0u;
            __threadfence();
            g_done = 0u;
        }
    }
}

// ---------------------------------------------------------------------------
extern "C" void kernel_launch(void* const* d_in, const int* in_sizes, int n_in,
                              void* d_out, int out_size) {
    const int*   x    = (const int*)d_in[0];
    const int*   ea   = (const int*)d_in[1];
    const float* bn   = (const float*)d_in[2];
    const float* aemb = (const float*)d_in[3];
    const float* bemb = (const float*)d_in[4];
    const float* Wi_w = (const float*)d_in[5];
    const float* Wi_b = (const float*)d_in[6];
    const float* Wm_w = (const float*)d_in[7];
    const float* Wm_b = (const float*)d_in[8];

    // Only the last layer (i = 2) affects the output.
    const float* Wi_w2 = Wi_w + 2 * 128 * 256;
    const float* Wi_b2 = Wi_b + 2 * 128;
    const float* Wm_w2 = Wm_w + 2 * 128 * 128;
    const float* Wm_b2 = Wm_b + 2 * 128;

    const int smem = (64 * 129 + 128 * 64) * (int)sizeof(float);  // 65,792 B
    static bool attr_set = false;
    if (!attr_set) {
        cudaFuncSetAttribute(k_all, cudaFuncAttributeMaxDynamicSharedMemorySize, smem);
        attr_set = true;
    }

    k_all<<<NBLK, 256, smem>>>(bn, x, ea, aemb, bemb,
                               Wi_w2, Wi_b2, Wm_w2, Wm_b2, (float*)d_out);
}

// round 8
// speedup vs baseline: 1.0369x; 1.0369x over previous
#include <cuda_runtime.h>
#include <cuda_bf16.h>

#define NN 16384      // nodes/edges (and bond_n rows A = 16384)
#define DD 128        // emb dim
// Only layer i = 2 matters: the reference loop does not feed h back.

#define NBLK 296      // 2 blocks per SM on 148 SMs, single wave

// Scratch (device globals — zero-initialized at module load; g_colw is
// re-zeroed by k_out each run so every graph replay starts from zero)
__device__ float g_colw[NN];
__device__ float g_hn[(size_t)NN * DD];      // 8 MB
__device__ float g_mpartT[DD][256];          // m partials, contiguous per d
__device__ float g_mm[DD];
__device__ unsigned g_cnt;                   // k_m last-block counter (self-resets)

// ---------------------------------------------------------------------------
// k_all, 296 blocks (one wave @ 2/SM). No in-kernel cross-block sync at all.
//   blocks [0,128):  GEMM h_n = relu(cat @ Wi_w[2].T + b) -> g_hn,
//                    then stream 51 rows of bond_n (row-contiguous).
//   blocks [128,296): stream 58-59 rows.
//   end of stream: REDG-atomicAdd the 16384 register column partials into
//   g_colw (pre-zeroed by previous run's k_out / module load).
// ---------------------------------------------------------------------------
__global__ void __launch_bounds__(256, 2) k_all(
    const float* __restrict__ bn,
    const int* __restrict__ x, const int* __restrict__ ea,
    const float* __restrict__ aemb, const float* __restrict__ bemb,
    const float* __restrict__ Wi_w2, const float* __restrict__ Wi_b2)
{
    extern __shared__ float sm[];
    const int tid = threadIdx.x;
    const int bid = blockIdx.x;

    // ---- static row shares for the bond_n stream (sum = 16384) ----
    int start, cnt;
    if (bid < 128)          { start = bid * 51;                 cnt = 51; }
    else if (bid < 240)     { start = 6528  + (bid - 128) * 59; cnt = 59; }
    else                    { start = 13136 + (bid - 240) * 58; cnt = 58; }

    if (bid < 128) {
        // ---------------- GEMM phase ----------------
        float* w_s   = sm;                 // [64][129] = 33,024 B
        float* cat_s = sm + 64 * 129;      // [128][64] = 32,768 B
        __shared__ float bias_s[128];
        __shared__ int xi0[128], xi1[128], ei0[128], ei1[128];

        const int rowBase = bid * 128;
        if (tid < 128) {
            bias_s[tid] = Wi_b2[tid];
            int r = rowBase + tid;
            xi0[tid] = x[2 * r];  xi1[tid] = x[2 * r + 1];
            ei0[tid] = ea[2 * r]; ei1[tid] = ea[2 * r + 1];
        }
        __syncthreads();

        const int tx = tid & 15, ty = tid >> 4;
        float acc[8][8];
#pragma unroll
        for (int i = 0; i < 8; i++)
#pragma unroll
            for (int j = 0; j < 8; j++) acc[i][j] = 0.f;

        for (int kc = 0; kc < 256; kc += 64) {
            for (int idx = tid; idx < 8192; idx += 256) {
                int d = idx >> 6, kk = idx & 63;
                w_s[kk * 129 + d] = Wi_w2[d * 256 + kc + kk];
            }
            const bool atom = (kc < 128);
            const float* emb = atom ? aemb : bemb;
            for (int idx = tid; idx < 2048; idx += 256) {
                int row  = idx >> 4;
                int kloc = (idx & 15) * 4;
                int i0 = atom ? xi0[row] : ei0[row];
                int i1 = atom ? xi1[row] : ei1[row];
                int ko = atom ? (kc + kloc) : (kc - 128 + kloc);
                float4 v0 = *(const float4*)(emb + i0 * 128 + ko);
                float4 v1 = *(const float4*)(emb + i1 * 128 + ko);
                float4 s;
                s.x = v0.x + v1.x; s.y = v0.y + v1.y;
                s.z = v0.z + v1.z; s.w = v0.w + v1.w;
                *(float4*)(cat_s + row * 64 + kloc) = s;
            }
            __syncthreads();

#pragma unroll 8
            for (int kk = 0; kk < 64; kk++) {
                const float* wr = w_s + kk * 129;
                float b[8], a[8];
#pragma unroll
                for (int j = 0; j < 8; j++) b[j] = wr[tx + 16 * j];
#pragma unroll
                for (int i = 0; i < 8; i++) a[i] = cat_s[(ty + 16 * i) * 64 + kk];
#pragma unroll
                for (int i = 0; i < 8; i++)
#pragma unroll
                    for (int j = 0; j < 8; j++)
                        acc[i][j] = fmaf(a[i], b[j], acc[i][j]);
            }
            __syncthreads();
        }

        // bias + relu -> g_hn
#pragma unroll
        for (int i = 0; i < 8; i++) {
            int r = ty + 16 * i;
#pragma unroll
            for (int j = 0; j < 8; j++) {
                int d = tx + 16 * j;
                float v = acc[i][j] + bias_s[d];
                g_hn[(size_t)(rowBase + r) * 128 + d] = v > 0.f ? v : 0.f;
            }
        }
    }

    // ---------------- bond_n streaming (ALL blocks) ----------------
    float4 acc[16];
#pragma unroll
    for (int i = 0; i < 16; i++) acc[i] = make_float4(0.f, 0.f, 0.f, 0.f);

    for (int r = 0; r < cnt; r++) {
        const float4* rp = (const float4*)(bn + (size_t)(start + r) * NN) + tid;
#pragma unroll
        for (int i = 0; i < 16; i++) {
            float4 v = __ldcs(rp + i * 256);
            acc[i].x += v.x; acc[i].y += v.y; acc[i].z += v.z; acc[i].w += v.w;
        }
    }

    // spread-address REDG adds: column base = (tid + i*256)*4
#pragma unroll
    for (int i = 0; i < 16; i++) {
        int c = (tid + i * 256) * 4;
        atomicAdd(&g_colw[c + 0], acc[i].x);
        atomicAdd(&g_colw[c + 1], acc[i].y);
        atomicAdd(&g_colw[c + 2], acc[i].z);
        atomicAdd(&g_colw[c + 3], acc[i].w);
    }
}

// ---------------------------------------------------------------------------
// k_m, 256 blocks: m partial over 64 rows each -> g_mpartT[d][b];
// last block reduces 256 contiguous partials per d + mm = m@Wm^T + b.
// Fresh kernel -> implicit global barrier, full parallelism, cheap tail.
// ---------------------------------------------------------------------------
__global__ void __launch_bounds__(256) k_m(const float* __restrict__ Wm_w2,
                                           const float* __restrict__ Wm_b2) {
    __shared__ float colw_s[64];
    __shared__ float red[256];
    __shared__ float ms[128];
    __shared__ bool last;

    const int b = blockIdx.x, tid = threadIdx.x;
    const int d = tid & 127, half = tid >> 7;
    const int rowBase = b * 64;

    if (tid < 64) colw_s[tid] = g_colw[rowBase + tid];
    __syncthreads();

    // m partial: rows [rowBase + half*32, +32)
    {
        float p = 0.f;
#pragma unroll 16
        for (int r = 0; r < 32; r++) {
            int row = half * 32 + r;
            p = fmaf(colw_s[row], g_hn[(size_t)(rowBase + row) * DD + d], p);
        }
        red[tid] = p;
    }
    __syncthreads();
    if (tid < 128) g_mpartT[tid][b] = red[tid] + red[tid + 128];
    __threadfence();
    if (tid == 0) last = (atomicAdd(&g_cnt, 1u) == 255u);
    __syncthreads();

    if (last) {
        if (tid < 128) {
            const float4* mp = (const float4*)g_mpartT[tid];
            float s = 0.f;
#pragma unroll 32
            for (int w = 0; w < 64; w++) {
                float4 v = __ldcg(mp + w);
                s += v.x + v.y + v.z + v.w;
            }
            ms[tid] = s;
        }
        __syncthreads();
        if (tid < 128) {
            float s = Wm_b2[tid];
            const float* row = Wm_w2 + tid * 128;
#pragma unroll 8
            for (int k = 0; k < 128; k++) s = fmaf(ms[k], __ldg(row + k), s);
            g_mm[tid] = s;
        }
        if (tid == 0) g_cnt = 0u;   // reset for next graph replay
    }
}

// ---------------------------------------------------------------------------
// k_out, 2048 blocks: out = relu(h_n + mm[broadcast]).
// Blocks 0..63 ALSO re-zero g_colw for the next graph replay (determinism:
// every run leaves g_colw = 0 at exit; module load provides run-1 zeros).
// ---------------------------------------------------------------------------
__global__ void __launch_bounds__(256) k_out(float* __restrict__ out) {
    __shared__ float mm[128];
    if (threadIdx.x < 128) mm[threadIdx.x] = g_mm[threadIdx.x];
    __syncthreads();

    if (blockIdx.x < 64) g_colw[blockIdx.x * 256 + threadIdx.x] = 0.f;

    size_t i = (size_t)blockIdx.x * 256 + threadIdx.x;   // float4 index
    float4 v = *(const float4*)(g_hn + i * 4);
    int d0 = (int)((i * 4) & 127);
    v.x = fmaxf(v.x + mm[d0 + 0], 0.f);
    v.y = fmaxf(v.y + mm[d0 + 1], 0.f);
    v.z = fmaxf(v.z + mm[d0 + 2], 0.f);
    v.w = fmaxf(v.w + mm[d0 + 3], 0.f);
    *((float4*)out + i) = v;
}

// ---------------------------------------------------------------------------
extern "C" void kernel_launch(void* const* d_in, const int* in_sizes, int n_in,
                              void* d_out, int out_size) {
    const int*   x    = (const int*)d_in[0];
    const int*   ea   = (const int*)d_in[1];
    const float* bn   = (const float*)d_in[2];
    const float* aemb = (const float*)d_in[3];
    const float* bemb = (const float*)d_in[4];
    const float* Wi_w = (const float*)d_in[5];
    const float* Wi_b = (const float*)d_in[6];
    const float* Wm_w = (const float*)d_in[7];
    const float* Wm_b = (const float*)d_in[8];

    // Only the last layer (i = 2) affects the output.
    const float* Wi_w2 = Wi_w + 2 * 128 * 256;
    const float* Wi_b2 = Wi_b + 2 * 128;
    const float* Wm_w2 = Wm_w + 2 * 128 * 128;
    const float* Wm_b2 = Wm_b + 2 * 128;

    const int smem = (64 * 129 + 128 * 64) * (int)sizeof(float);  // 65,792 B
    static bool attr_set = false;
    if (!attr_set) {
        cudaFuncSetAttribute(k_all, cudaFuncAttributeMaxDynamicSharedMemorySize, smem);
        attr_set = true;
    }

    k_all<<<NBLK, 256, smem>>>(bn, x, ea, aemb, bemb, Wi_w2, Wi_b2);
    k_m<<<256, 256>>>(Wm_w2, Wm_b2);
    k_out<<<2048, 256>>>((float*)d_out);
}

// round 9
// speedup vs baseline: 1.0429x; 1.0058x over previous
#include <cuda_runtime.h>
#include <cuda_bf16.h>

#define NN 16384      // nodes/edges (and bond_n rows A = 16384)
#define DD 128        // emb dim
// Only layer i = 2 matters: the reference loop does not feed h back.

#define NBLK 296      // 2 blocks per SM on 148 SMs, single wave

// Scratch (device globals — zero-initialized at module load; g_colw is
// re-zeroed by k_out each run so every graph replay starts from zero)
__device__ float g_colw[NN];
__device__ float g_hn[(size_t)NN * DD];      // 8 MB
__device__ float g_mpartT[DD][256];          // m partials, contiguous per d
__device__ float g_mm[DD];
__device__ unsigned g_cnt;                   // k_m last-block counter (self-resets)

// ---------------------------------------------------------------------------
// k_all, 296 blocks (one wave @ 2/SM). No in-kernel cross-block sync at all.
//   blocks [0,128):  GEMM h_n = relu(cat @ Wi_w[2].T + b) -> g_hn,
//                    then stream 51 rows of bond_n (row-contiguous).
//   blocks [128,296): stream 58-59 rows.
//   end of stream: REDG-atomicAdd the 16384 register column partials into
//   g_colw (pre-zeroed by previous run's k_out / module load).
// ---------------------------------------------------------------------------
__global__ void __launch_bounds__(256, 2) k_all(
    const float* __restrict__ bn,
    const int* __restrict__ x, const int* __restrict__ ea,
    const float* __restrict__ aemb, const float* __restrict__ bemb,
    const float* __restrict__ Wi_w2, const float* __restrict__ Wi_b2)
{
    extern __shared__ float sm[];
    const int tid = threadIdx.x;
    const int bid = blockIdx.x;

    // ---- static row shares for the bond_n stream (sum = 16384) ----
    int start, cnt;
    if (bid < 128)          { start = bid * 51;                 cnt = 51; }
    else if (bid < 240)     { start = 6528  + (bid - 128) * 59; cnt = 59; }
    else                    { start = 13136 + (bid - 240) * 58; cnt = 58; }

    if (bid < 128) {
        // ---------------- GEMM phase ----------------
        float* w_s   = sm;                 // [64][129] = 33,024 B
        float* cat_s = sm + 64 * 129;      // [128][64] = 32,768 B
        __shared__ float bias_s[128];
        __shared__ int xi0[128], xi1[128], ei0[128], ei1[128];

        const int rowBase = bid * 128;
        if (tid < 128) {
            bias_s[tid] = Wi_b2[tid];
            int r = rowBase + tid;
            xi0[tid] = x[2 * r];  xi1[tid] = x[2 * r + 1];
            ei0[tid] = ea[2 * r]; ei1[tid] = ea[2 * r + 1];
        }
        __syncthreads();

        const int tx = tid & 15, ty = tid >> 4;
        float acc[8][8];
#pragma unroll
        for (int i = 0; i < 8; i++)
#pragma unroll
            for (int j = 0; j < 8; j++) acc[i][j] = 0.f;

        for (int kc = 0; kc < 256; kc += 64) {
            for (int idx = tid; idx < 8192; idx += 256) {
                int d = idx >> 6, kk = idx & 63;
                w_s[kk * 129 + d] = Wi_w2[d * 256 + kc + kk];
            }
            const bool atom = (kc < 128);
            const float* emb = atom ? aemb : bemb;
            for (int idx = tid; idx < 2048; idx += 256) {
                int row  = idx >> 4;
                int kloc = (idx & 15) * 4;
                int i0 = atom ? xi0[row] : ei0[row];
                int i1 = atom ? xi1[row] : ei1[row];
                int ko = atom ? (kc + kloc) : (kc - 128 + kloc);
                float4 v0 = *(const float4*)(emb + i0 * 128 + ko);
                float4 v1 = *(const float4*)(emb + i1 * 128 + ko);
                float4 s;
                s.x = v0.x + v1.x; s.y = v0.y + v1.y;
                s.z = v0.z + v1.z; s.w = v0.w + v1.w;
                *(float4*)(cat_s + row * 64 + kloc) = s;
            }
            __syncthreads();

#pragma unroll 8
            for (int kk = 0; kk < 64; kk++) {
                const float* wr = w_s + kk * 129;
                float b[8], a[8];
#pragma unroll
                for (int j = 0; j < 8; j++) b[j] = wr[tx + 16 * j];
#pragma unroll
                for (int i = 0; i < 8; i++) a[i] = cat_s[(ty + 16 * i) * 64 + kk];
#pragma unroll
                for (int i = 0; i < 8; i++)
#pragma unroll
                    for (int j = 0; j < 8; j++)
                        acc[i][j] = fmaf(a[i], b[j], acc[i][j]);
            }
            __syncthreads();
        }

        // bias + relu -> g_hn
#pragma unroll
        for (int i = 0; i < 8; i++) {
            int r = ty + 16 * i;
#pragma unroll
            for (int j = 0; j < 8; j++) {
                int d = tx + 16 * j;
                float v = acc[i][j] + bias_s[d];
                g_hn[(size_t)(rowBase + r) * 128 + d] = v > 0.f ? v : 0.f;
            }
        }
    }

    // ---------------- bond_n streaming (ALL blocks) ----------------
    float4 acc[16];
#pragma unroll
    for (int i = 0; i < 16; i++) acc[i] = make_float4(0.f, 0.f, 0.f, 0.f);

    for (int r = 0; r < cnt; r++) {
        const float4* rp = (const float4*)(bn + (size_t)(start + r) * NN) + tid;
#pragma unroll
        for (int i = 0; i < 16; i++) {
            float4 v = __ldcs(rp + i * 256);
            acc[i].x += v.x; acc[i].y += v.y; acc[i].z += v.z; acc[i].w += v.w;
        }
    }

    // spread-address REDG adds: column base = (tid + i*256)*4
#pragma unroll
    for (int i = 0; i < 16; i++) {
        int c = (tid + i * 256) * 4;
        atomicAdd(&g_colw[c + 0], acc[i].x);
        atomicAdd(&g_colw[c + 1], acc[i].y);
        atomicAdd(&g_colw[c + 2], acc[i].z);
        atomicAdd(&g_colw[c + 3], acc[i].w);
    }
}

// ---------------------------------------------------------------------------
// k_m, 256 blocks: m partial over 64 rows each -> g_mpartT[d][b];
// last block reduces 256 contiguous partials per d + mm = m@Wm^T + b.
// Fresh kernel -> implicit global barrier, full parallelism, cheap tail.
// ---------------------------------------------------------------------------
__global__ void __launch_bounds__(256) k_m(const float* __restrict__ Wm_w2,
                                           const float* __restrict__ Wm_b2) {
    __shared__ float colw_s[64];
    __shared__ float red[256];
    __shared__ float ms[128];
    __shared__ bool last;

    const int b = blockIdx.x, tid = threadIdx.x;
    const int d = tid & 127, half = tid >> 7;
    const int rowBase = b * 64;

    if (tid < 64) colw_s[tid] = g_colw[rowBase + tid];
    __syncthreads();

    // m partial: rows [rowBase + half*32, +32)
    {
        float p = 0.f;
#pragma unroll 16
        for (int r = 0; r < 32; r++) {
            int row = half * 32 + r;
            p = fmaf(colw_s[row], g_hn[(size_t)(rowBase + row) * DD + d], p);
        }
        red[tid] = p;
    }
    __syncthreads();
    if (tid < 128) g_mpartT[tid][b] = red[tid] + red[tid + 128];
    __threadfence();
    if (tid == 0) last = (atomicAdd(&g_cnt, 1u) == 255u);
    __syncthreads();

    if (last) {
        if (tid < 128) {
            const float4* mp = (const float4*)g_mpartT[tid];
            float s = 0.f;
#pragma unroll 32
            for (int w = 0; w < 64; w++) {
                float4 v = __ldcg(mp + w);
                s += v.x + v.y + v.z + v.w;
            }
            ms[tid] = s;
        }
        __syncthreads();
        if (tid < 128) {
            float s = Wm_b2[tid];
            const float* row = Wm_w2 + tid * 128;
#pragma unroll 8
            for (int k = 0; k < 128; k++) s = fmaf(ms[k], __ldg(row + k), s);
            g_mm[tid] = s;
        }
        if (tid == 0) g_cnt = 0u;   // reset for next graph replay
    }
}

// ---------------------------------------------------------------------------
// k_out, 2048 blocks: out = relu(h_n + mm[broadcast]).
// Blocks 0..63 ALSO re-zero g_colw for the next graph replay (determinism:
// every run leaves g_colw = 0 at exit; module load provides run-1 zeros).
// ---------------------------------------------------------------------------
__global__ void __launch_bounds__(256) k_out(float* __restrict__ out) {
    __shared__ float mm[128];
    if (threadIdx.x < 128) mm[threadIdx.x] = g_mm[threadIdx.x];
    __syncthreads();

    if (blockIdx.x < 64) g_colw[blockIdx.x * 256 + threadIdx.x] = 0.f;

    size_t i = (size_t)blockIdx.x * 256 + threadIdx.x;   // float4 index
    float4 v = *(const float4*)(g_hn + i * 4);
    int d0 = (int)((i * 4) & 127);
    v.x = fmaxf(v.x + mm[d0 + 0], 0.f);
    v.y = fmaxf(v.y + mm[d0 + 1], 0.f);
    v.z = fmaxf(v.z + mm[d0 + 2], 0.f);
    v.w = fmaxf(v.w + mm[d0 + 3], 0.f);
    *((float4*)out + i) = v;
}

// ---------------------------------------------------------------------------
extern "C" void kernel_launch(void* const* d_in, const int* in_sizes, int n_in,
                              void* d_out, int out_size) {
    const int*   x    = (const int*)d_in[0];
    const int*   ea   = (const int*)d_in[1];
    const float* bn   = (const float*)d_in[2];
    const float* aemb = (const float*)d_in[3];
    const float* bemb = (const float*)d_in[4];
    const float* Wi_w = (const float*)d_in[5];
    const float* Wi_b = (const float*)d_in[6];
    const float* Wm_w = (const float*)d_in[7];
    const float* Wm_b = (const float*)d_in[8];

    // Only the last layer (i = 2) affects the output.
    const float* Wi_w2 = Wi_w + 2 * 128 * 256;
    const float* Wi_b2 = Wi_b + 2 * 128;
    const float* Wm_w2 = Wm_w + 2 * 128 * 128;
    const float* Wm_b2 = Wm_b + 2 * 128;

    const int smem = (64 * 129 + 128 * 64) * (int)sizeof(float);  // 65,792 B
    static bool attr_set = false;
    if (!attr_set) {
        cudaFuncSetAttribute(k_all, cudaFuncAttributeMaxDynamicSharedMemorySize, smem);
        attr_set = true;
    }

    k_all<<<NBLK, 256, smem>>>(bn, x, ea, aemb, bemb, Wi_w2, Wi_b2);
    k_m<<<256, 256>>>(Wm_w2, Wm_b2);
    k_out<<<2048, 256>>>((float*)d_out);
}

// round 10
// speedup vs baseline: 1.0827x; 1.0382x over previous
#include <cuda_runtime.h>
#include <cuda_bf16.h>

#define NN 16384      // nodes/edges (and bond_n rows A = 16384)
#define DD 128        // emb dim
// Only layer i = 2 matters: the reference loop does not feed h back.

#define RSPLIT 9216   // stream blocks: rows [0,9216); GEMM blocks: [9216,16384)

// Scratch (device globals)
__device__ float g_colw2[2][NN];             // two deterministic partial slots
__device__ float g_hn[(size_t)NN * DD];      // 8 MB
__device__ float g_mpartT[DD][256];          // m partials, contiguous per d
__device__ float g_mm[DD];
__device__ unsigned g_cnt;                   // k_m last-block counter (self-resets)

// ---------------------------------------------------------------------------
// Column-slice partial sum: cols [slice*128, +128), rows [r0, r1), warp-strided.
// (r1-r0) must be divisible by 128 (8 warps x unroll 16).
// ---------------------------------------------------------------------------
__device__ __forceinline__ void colsum_slice(
    const float* __restrict__ bn, float* sm, int slice, int r0, int r1,
    int slot, int tid)
{
    const int lane = tid & 31, warp = tid >> 5;
    const float* base = bn + (size_t)(r0 + warp) * NN + slice * 128 + lane * 4;
    const int iters = (r1 - r0) >> 3;              // per-warp row count
    float4 a0 = {0,0,0,0}, a1 = {0,0,0,0}, a2 = {0,0,0,0}, a3 = {0,0,0,0};
    for (int i = 0; i < iters; i += 16) {
#pragma unroll
        for (int u = 0; u < 16; u++) {
            float4 v = __ldcs((const float4*)(base + (size_t)(i + u) * 8 * NN));
            float4& a = (u & 3) == 0 ? a0 : (u & 3) == 1 ? a1 : (u & 3) == 2 ? a2 : a3;
            a.x += v.x; a.y += v.y; a.z += v.z; a.w += v.w;
        }
    }
    float sx = a0.x + a1.x + a2.x + a3.x;
    float sy = a0.y + a1.y + a2.y + a3.y;
    float sz = a0.z + a1.z + a2.z + a3.z;
    float sw = a0.w + a1.w + a2.w + a3.w;
    // cross-warp reduce: part[8][128] in (reused) dynamic smem
    float* part = sm;
    __syncthreads();                                // smem may be GEMM-dirty
    part[warp * 128 + lane * 4 + 0] = sx;
    part[warp * 128 + lane * 4 + 1] = sy;
    part[warp * 128 + lane * 4 + 2] = sz;
    part[warp * 128 + lane * 4 + 3] = sw;
    __syncthreads();
    if (tid < 128) {
        float s = 0.f;
#pragma unroll
        for (int w = 0; w < 8; w++) s += part[w * 128 + tid];
        g_colw2[slot][slice * 128 + tid] = s;
    }
}

// ---------------------------------------------------------------------------
// k_fused, 256 blocks (one wave @ 2/SM), R2 structure + row-split rebalance:
//   blocks [0,128):   colsum slice=bid, rows [0, RSPLIT)        -> slot 0
//   blocks [128,256): GEMM (128 rows) then
//                     colsum slice=bid-128, rows [RSPLIT,16384) -> slot 1
// No atomics, no partial matrices, deterministic.
// ---------------------------------------------------------------------------
__global__ void __launch_bounds__(256) k_fused(
    const float* __restrict__ bn,
    const int* __restrict__ x, const int* __restrict__ ea,
    const float* __restrict__ aemb, const float* __restrict__ bemb,
    const float* __restrict__ Wi_w2, const float* __restrict__ Wi_b2)
{
    extern __shared__ float sm[];
    const int tid = threadIdx.x;
    const int bid = blockIdx.x;

    if (bid < 128) {
        colsum_slice(bn, sm, bid, 0, RSPLIT, 0, tid);
        return;
    }

    // ---------------- GEMM phase (blocks 128..255) ----------------
    {
        float* w_s   = sm;                 // [64][129] = 33,024 B (per-k chunk)
        float* cat_s = sm + 64 * 129;      // [128][64] = 32,768 B
        __shared__ float bias_s[128];
        __shared__ int xi0[128], xi1[128], ei0[128], ei1[128];

        const int rowBase = (bid - 128) * 128;
        if (tid < 128) {
            bias_s[tid] = Wi_b2[tid];
            int r = rowBase + tid;
            xi0[tid] = x[2 * r];  xi1[tid] = x[2 * r + 1];
            ei0[tid] = ea[2 * r]; ei1[tid] = ea[2 * r + 1];
        }
        __syncthreads();

        const int tx = tid & 15, ty = tid >> 4;
        float acc[8][8];
#pragma unroll
        for (int i = 0; i < 8; i++)
#pragma unroll
            for (int j = 0; j < 8; j++) acc[i][j] = 0.f;

        for (int kc = 0; kc < 256; kc += 64) {
            for (int idx = tid; idx < 8192; idx += 256) {
                int d = idx >> 6, kk = idx & 63;
                w_s[kk * 129 + d] = Wi_w2[d * 256 + kc + kk];
            }
            const bool atom = (kc < 128);
            const float* emb = atom ? aemb : bemb;
            for (int idx = tid; idx < 2048; idx += 256) {
                int row  = idx >> 4;
                int kloc = (idx & 15) * 4;
                int i0 = atom ? xi0[row] : ei0[row];
                int i1 = atom ? xi1[row] : ei1[row];
                int ko = atom ? (kc + kloc) : (kc - 128 + kloc);
                float4 v0 = *(const float4*)(emb + i0 * 128 + ko);
                float4 v1 = *(const float4*)(emb + i1 * 128 + ko);
                float4 s;
                s.x = v0.x + v1.x; s.y = v0.y + v1.y;
                s.z = v0.z + v1.z; s.w = v0.w + v1.w;
                *(float4*)(cat_s + row * 64 + kloc) = s;
            }
            __syncthreads();

#pragma unroll 8
            for (int kk = 0; kk < 64; kk++) {
                const float* wr = w_s + kk * 129;
                float b[8], a[8];
#pragma unroll
                for (int j = 0; j < 8; j++) b[j] = wr[tx + 16 * j];
#pragma unroll
                for (int i = 0; i < 8; i++) a[i] = cat_s[(ty + 16 * i) * 64 + kk];
#pragma unroll
                for (int i = 0; i < 8; i++)
#pragma unroll
                    for (int j = 0; j < 8; j++)
                        acc[i][j] = fmaf(a[i], b[j], acc[i][j]);
            }
            __syncthreads();
        }

        // bias + relu -> g_hn
#pragma unroll
        for (int i = 0; i < 8; i++) {
            int r = ty + 16 * i;
#pragma unroll
            for (int j = 0; j < 8; j++) {
                int d = tx + 16 * j;
                float v = acc[i][j] + bias_s[d];
                g_hn[(size_t)(rowBase + r) * 128 + d] = v > 0.f ? v : 0.f;
            }
        }
    }

    // ---------------- colsum tail: bottom rows of the same slice ----------------
    colsum_slice(bn, sm, bid - 128, RSPLIT, NN, 1, tid);
}

// ---------------------------------------------------------------------------
// k_m, 256 blocks: colw = slot0 + slot1; m partial over 64 rows each
// -> g_mpartT[d][b]; last block reduces + mm = m@Wm^T + b. Counter resets.
// ---------------------------------------------------------------------------
__global__ void __launch_bounds__(256) k_m(const float* __restrict__ Wm_w2,
                                           const float* __restrict__ Wm_b2) {
    __shared__ float colw_s[64];
    __shared__ float red[256];
    __shared__ float ms[128];
    __shared__ bool last;

    const int b = blockIdx.x, tid = threadIdx.x;
    const int d = tid & 127, half = tid >> 7;
    const int rowBase = b * 64;

    if (tid < 64) colw_s[tid] = g_colw2[0][rowBase + tid] + g_colw2[1][rowBase + tid];
    __syncthreads();

    {
        float p = 0.f;
#pragma unroll 16
        for (int r = 0; r < 32; r++) {
            int row = half * 32 + r;
            p = fmaf(colw_s[row], g_hn[(size_t)(rowBase + row) * DD + d], p);
        }
        red[tid] = p;
    }
    __syncthreads();
    if (tid < 128) g_mpartT[tid][b] = red[tid] + red[tid + 128];
    __threadfence();
    if (tid == 0) last = (atomicAdd(&g_cnt, 1u) == 255u);
    __syncthreads();

    if (last) {
        if (tid < 128) {
            const float4* mp = (const float4*)g_mpartT[tid];
            float s = 0.f;
#pragma unroll 32
            for (int w = 0; w < 64; w++) {
                float4 v = __ldcg(mp + w);
                s += v.x + v.y + v.z + v.w;
            }
            ms[tid] = s;
        }
        __syncthreads();
        if (tid < 128) {
            float s = Wm_b2[tid];
            const float* row = Wm_w2 + tid * 128;
#pragma unroll 8
            for (int k = 0; k < 128; k++) s = fmaf(ms[k], __ldg(row + k), s);
            g_mm[tid] = s;
        }
        if (tid == 0) g_cnt = 0u;   // reset for next graph replay
    }
}

// ---------------------------------------------------------------------------
// k_out, 2048 blocks: out = relu(h_n + mm[broadcast]).
// ---------------------------------------------------------------------------
__global__ void __launch_bounds__(256) k_out(float* __restrict__ out) {
    __shared__ float mm[128];
    if (threadIdx.x < 128) mm[threadIdx.x] = g_mm[threadIdx.x];
    __syncthreads();
    size_t i = (size_t)blockIdx.x * 256 + threadIdx.x;   // float4 index
    float4 v = *(const float4*)(g_hn + i * 4);
    int d0 = (int)((i * 4) & 127);
    v.x = fmaxf(v.x + mm[d0 + 0], 0.f);
    v.y = fmaxf(v.y + mm[d0 + 1], 0.f);
    v.z = fmaxf(v.z + mm[d0 + 2], 0.f);
    v.w = fmaxf(v.w + mm[d0 + 3], 0.f);
    *((float4*)out + i) = v;
}

// ---------------------------------------------------------------------------
extern "C" void kernel_launch(void* const* d_in, const int* in_sizes, int n_in,
                              void* d_out, int out_size) {
    const int*   x    = (const int*)d_in[0];
    const int*   ea   = (const int*)d_in[1];
    const float* bn   = (const float*)d_in[2];
    const float* aemb = (const float*)d_in[3];
    const float* bemb = (const float*)d_in[4];
    const float* Wi_w = (const float*)d_in[5];
    const float* Wi_b = (const float*)d_in[6];
    const float* Wm_w = (const float*)d_in[7];
    const float* Wm_b = (const float*)d_in[8];

    // Only the last layer (i = 2) affects the output.
    const float* Wi_w2 = Wi_w + 2 * 128 * 256;
    const float* Wi_b2 = Wi_b + 2 * 128;
    const float* Wm_w2 = Wm_w + 2 * 128 * 128;
    const float* Wm_b2 = Wm_b + 2 * 128;

    const int smem = (64 * 129 + 128 * 64) * (int)sizeof(float);  // 65,792 B
    static bool attr_set = false;
    if (!attr_set) {
        cudaFuncSetAttribute(k_fused, cudaFuncAttributeMaxDynamicSharedMemorySize, smem);
        attr_set = true;
    }

    k_fused<<<256, 256, smem>>>(bn, x, ea, aemb, bemb, Wi_w2, Wi_b2);
    k_m<<<256, 256>>>(Wm_w2, Wm_b2);
    k_out<<<2048, 256>>>((float*)d_out);
}